// round 1
// baseline (speedup 1.0000x reference)
#include <cuda_runtime.h>

// Problem constants (fixed per metadata)
#define PP 8      // personas
#define FF 64     // factor dim
#define TPB 224   // 7 warps; one lane per item slot (S=200 <= 224)
#define NW  (TPB/32)
#define VSTR 68   // padded f32 stride per v row: 16B-aligned rows, conflict-free LDS.128

__global__ __launch_bounds__(TPB) void cf_kernel(
    const int*   __restrict__ user,     // [B]
    const int*   __restrict__ items,    // [B,S]
    const float* __restrict__ ufac,     // [N_USERS, PP, FF]
    const float* __restrict__ ifac,     // [N_ITEMS, FF]
    float*       __restrict__ pred,     // [B,S]
    float*       __restrict__ scores,   // [B,S,PP]
    int B, int S)
{
    __shared__ float s_u[PP * FF];
    extern __shared__ float s_v[];      // [S * VSTR]

    const int b    = blockIdx.x;
    const int tid  = threadIdx.x;
    const int warp = tid >> 5;
    const int lane = tid & 31;

    // Stage user persona factors: 512 floats, coalesced.
    const float* ub = ufac + (long long)__ldg(&user[b]) * (PP * FF);
    for (int i = tid; i < PP * FF; i += TPB) s_u[i] = ub[i];

    // Stage all S item rows: one warp per row, float2 per lane (full 256B row / warp-load).
    const int* itr = items + (long long)b * S;
    for (int r = warp; r < S; r += NW) {
        const float2* vrow = (const float2*)(ifac + (long long)__ldg(&itr[r]) * FF);
        float2 v2 = vrow[lane];
        s_v[r * VSTR + 2 * lane]     = v2.x;
        s_v[r * VSTR + 2 * lane + 1] = v2.y;
    }
    __syncthreads();

    const int s = tid;
    if (s < S) {
        float acc[PP];
        #pragma unroll
        for (int p = 0; p < PP; p++) acc[p] = 0.f;

        const float* vr = s_v + s * VSTR;
        #pragma unroll
        for (int f = 0; f < FF; f += 4) {
            const float4 v4 = *(const float4*)(vr + f);                 // per-lane row, banks spread by pad
            #pragma unroll
            for (int p = 0; p < PP; p++) {
                const float4 u4 = *(const float4*)(s_u + p * FF + f);   // broadcast (all lanes same addr)
                acc[p] += v4.x * u4.x + v4.y * u4.y + v4.z * u4.z + v4.w * u4.w;
            }
        }

        // softmax over 8 personas + pred = sum_p a_p * r_p
        float m = acc[0];
        #pragma unroll
        for (int p = 1; p < PP; p++) m = fmaxf(m, acc[p]);
        float e[PP], sum = 0.f;
        #pragma unroll
        for (int p = 0; p < PP; p++) { e[p] = __expf(acc[p] - m); sum += e[p]; }
        const float inv = 1.f / sum;

        float a[PP], pr = 0.f;
        #pragma unroll
        for (int p = 0; p < PP; p++) { a[p] = e[p] * inv; pr += a[p] * acc[p]; }

        pred[(long long)b * S + s] = pr;
        float4* so = (float4*)(scores + ((long long)b * S + s) * (long long)PP);
        so[0] = make_float4(a[0], a[1], a[2], a[3]);
        so[1] = make_float4(a[4], a[5], a[6], a[7]);
    }
}

extern "C" void kernel_launch(void* const* d_in, const int* in_sizes, int n_in,
                              void* d_out, int out_size) {
    const int*   user  = (const int*)d_in[0];
    const int*   items = (const int*)d_in[1];
    const float* ufac  = (const float*)d_in[2];
    const float* ifac  = (const float*)d_in[3];

    const int B = in_sizes[0];
    const int S = in_sizes[1] / B;

    float* out    = (float*)d_out;
    float* pred   = out;                       // [B,S]
    float* scores = out + (long long)B * S;    // [B,S,PP]

    const int smem = S * VSTR * (int)sizeof(float);   // 54,400 B for S=200
    cudaFuncSetAttribute(cf_kernel, cudaFuncAttributeMaxDynamicSharedMemorySize, smem);

    cf_kernel<<<B, TPB, smem>>>(user, items, ufac, ifac, pred, scores, B, S);
}

// round 2
// speedup vs baseline: 1.0761x; 1.0761x over previous
#include <cuda_runtime.h>

#define PP   8       // personas
#define FF   64      // factor dim (floats per item row)
#define SB   200     // S (items per batch row)
#define TPB  224     // 7 warps
#define NW   7
#define RPB  2       // batch rows per CTA

// Dynamic smem: v tiles for 2 batches, 400 rows x 64 floats, XOR-swizzled (no pad).
// Static smem: u for 2 batches (4KB).

__global__ __launch_bounds__(TPB) void cf_kernel(
    const int*   __restrict__ user,     // [B]
    const int*   __restrict__ items,    // [B,SB]
    const float* __restrict__ ufac,     // [N_USERS, PP, FF]
    const float* __restrict__ ifac,     // [N_ITEMS, FF]
    float*       __restrict__ pred,     // [B,SB]
    float*       __restrict__ scores,   // [B,SB,PP]
    int B)
{
    __shared__ float s_u[RPB * PP * FF];     // 4 KB
    extern __shared__ float s_v[];           // RPB*SB*FF floats = 102,400 B

    const int tid  = threadIdx.x;
    const int warp = tid >> 5;
    const int lane = tid & 31;
    const long long b0 = (long long)blockIdx.x * RPB;
    const bool has_b1 = (b0 + 1) < B;

    // ---- Stage u for both batches: 256 float4, coalesced ----
    {
        const long long ubase0 = (long long)__ldg(&user[b0]) * (PP * FF);
        const long long ubase1 = has_b1 ? (long long)__ldg(&user[b0 + 1]) * (PP * FF) : ubase0;
        #pragma unroll
        for (int i = tid; i < RPB * PP * FF / 4; i += TPB) {
            const long long src = (i < 128 ? ubase0 : ubase1) + (long long)(i & 127) * 4;
            ((float4*)s_u)[i] = *(const float4*)(ufac + src);
        }
    }

    // ---- Gather v rows: 200 row-pairs, one pair per warp-iter (float4/lane, 16 lanes/row) ----
    // Combined row r in [0, 400): items index is items[b0*SB + r] (batches contiguous).
    const int c  = lane & 15;          // float4 chunk within row
    const int rh = lane >> 4;          // which row of the pair
    #pragma unroll
    for (int k = 0; k < 29; k++) {
        const int p = warp + NW * k;
        if (p < RPB * SB / 2) {
            const int r = (p << 1) + rh;
            if (has_b1 || r < SB) {
                const int idx = __ldg(&items[b0 * SB + r]);
                const float4 v4 = *(const float4*)(ifac + (long long)idx * FF + (c << 2));
                const int phys = (c ^ (r & 15)) << 2;           // XOR swizzle, conflict-free
                *(float4*)(s_v + r * FF + phys) = v4;
            }
        }
    }
    __syncthreads();

    // ---- Compute: thread t<200 handles rows (s0, s0+100) of batch bb ----
    if (tid < RPB * 100) {
        const int bb = tid / 100;
        const int s0 = tid - bb * 100;
        const int r0 = bb * SB + s0;
        const int r1 = r0 + 100;
        const long long b = b0 + bb;

        const float* ubase  = s_u + bb * PP * FF;
        const float* v0base = s_v + r0 * FF;
        const float* v1base = s_v + r1 * FF;
        const int m0 = (r0 & 15) << 2;
        const int m1 = (r1 & 15) << 2;

        float acc0[PP], acc1[PP];
        #pragma unroll
        for (int p = 0; p < PP; p++) { acc0[p] = 0.f; acc1[p] = 0.f; }

        #pragma unroll
        for (int cc = 0; cc < FF / 4; cc++) {
            const float4 v0 = *(const float4*)(v0base + ((cc << 2) ^ m0));
            const float4 v1 = *(const float4*)(v1base + ((cc << 2) ^ m1));
            #pragma unroll
            for (int p = 0; p < PP; p++) {
                const float4 u4 = *(const float4*)(ubase + p * FF + (cc << 2)); // broadcast
                acc0[p] = fmaf(v0.w, u4.w, fmaf(v0.z, u4.z, fmaf(v0.y, u4.y, fmaf(v0.x, u4.x, acc0[p]))));
                acc1[p] = fmaf(v1.w, u4.w, fmaf(v1.z, u4.z, fmaf(v1.y, u4.y, fmaf(v1.x, u4.x, acc1[p]))));
            }
        }

        if (b < B) {
            // softmax over 8 personas + pred = sum_p a_p * r_p (attentive_user·v == Σ a_p r_p)
            #pragma unroll 2
            for (int h = 0; h < 2; h++) {
                const float* acc = (h == 0) ? acc0 : acc1;
                const int s = s0 + h * 100;

                float m = acc[0];
                #pragma unroll
                for (int p = 1; p < PP; p++) m = fmaxf(m, acc[p]);
                float e[PP], sum = 0.f;
                #pragma unroll
                for (int p = 0; p < PP; p++) { e[p] = __expf(acc[p] - m); sum += e[p]; }
                const float inv = 1.f / sum;

                float a[PP], pr = 0.f;
                #pragma unroll
                for (int p = 0; p < PP; p++) { a[p] = e[p] * inv; pr = fmaf(a[p], acc[p], pr); }

                pred[b * SB + s] = pr;
                float4* so = (float4*)(scores + (b * SB + s) * (long long)PP);
                so[0] = make_float4(a[0], a[1], a[2], a[3]);
                so[1] = make_float4(a[4], a[5], a[6], a[7]);
            }
        }
    }
}

extern "C" void kernel_launch(void* const* d_in, const int* in_sizes, int n_in,
                              void* d_out, int out_size) {
    const int*   user  = (const int*)d_in[0];
    const int*   items = (const int*)d_in[1];
    const float* ufac  = (const float*)d_in[2];
    const float* ifac  = (const float*)d_in[3];

    const int B = in_sizes[0];

    float* out    = (float*)d_out;
    float* pred   = out;                        // [B,SB]
    float* scores = out + (long long)B * SB;    // [B,SB,PP]

    const int smem = RPB * SB * FF * (int)sizeof(float);   // 102,400 B
    cudaFuncSetAttribute(cf_kernel, cudaFuncAttributeMaxDynamicSharedMemorySize, smem);

    const int grid = (B + RPB - 1) / RPB;
    cf_kernel<<<grid, TPB, smem>>>(user, items, ufac, ifac, pred, scores, B);
}